// round 17
// baseline (speedup 1.0000x reference)
#include <cuda_runtime.h>
#include <math.h>

#define EDIM   256
#define HDIM   512
#define BATCH  32
#define SEQ    512
#define G3     1536
#define NCTA   128
#define GRUT   512
#define NG     4      // independent batch groups
#define CPG    32     // CTAs per group
#define BPG    8      // batches per group
#define DPC2   16     // dims per CTA

// ---- f32x2 packed helpers (sm_103a FFMA2; full fp32 precision) ----
__device__ __forceinline__ void fma2(unsigned long long& a,
                                     unsigned long long x, unsigned long long y) {
    asm("fma.rn.f32x2 %0, %1, %2, %0;" : "+l"(a) : "l"(x), "l"(y));
}
__device__ __forceinline__ float2 upk(unsigned long long v) {
    float2 r; asm("mov.b64 {%0, %1}, %2;" : "=f"(r.x), "=f"(r.y) : "l"(v));
    return r;
}
__device__ __forceinline__ void stcg(float* p, float v) {
    asm volatile("st.global.cg.f32 [%0], %1;" :: "l"(p), "f"(v));
}
__device__ __forceinline__ float4 ldcg4(const float4* p) {
    float4 v;
    asm volatile("ld.global.cg.v4.f32 {%0,%1,%2,%3}, [%4];"
                 : "=f"(v.x), "=f"(v.y), "=f"(v.z), "=f"(v.w) : "l"(p));
    return v;
}
__device__ __forceinline__ float tanh_ap(float x) {
    float y; asm("tanh.approx.f32 %0, %1;" : "=f"(y) : "f"(x));
    return y;
}

// ---- scratch (device globals; no allocations allowed) ----
__device__ float d_induced[EDIM];
__device__ float d_e2[SEQ * BATCH * EDIM];            // [t][b][k]
__device__ float d_xi[(size_t)SEQ * G3 * BATCH];      // [t][g][b]
__device__ float d_h3[2 * NG * BPG * HDIM];           // [buf][grp][b][d]
__device__ float d_pooled[BATCH * HDIM];              // [b][d]
__device__ unsigned d_cntg[NG * 32];                  // per-group arrival (128B apart)
__device__ unsigned d_geng[NG * 32];                  // per-group generation

// ---- init ----
__global__ void init_kernel(const float* __restrict__ induction,
                            const float* __restrict__ unk) {
    int i = threadIdx.x;                               // 256 threads
    if (i < NG * 32) { d_cntg[i] = 0u; d_geng[i] = 0u; }
    const float* row = induction + (size_t)i * EDIM;
    float s = 0.f;
    #pragma unroll 4
    for (int j = 0; j < EDIM; j++) s += row[j] * unk[j];
    d_induced[i] = s;
    for (int f = i; f < NG * BPG * HDIM; f += 256) d_h3[f] = 0.f;  // buf 0
}

// ---- gather: e2[t][b][:] = emb_table[tok] or induced ----
__global__ void gather_kernel(const int* __restrict__ x,
                              const float* __restrict__ emb) {
    int gid = blockIdx.x * 256 + threadIdx.x;          // one float4 each
    int row = gid >> 6;
    int q   = gid & 63;
    int t = row >> 5, b = row & 31;
    int tok = x[b * SEQ + t];
    float4 v;
    if (tok < 0) v = ((const float4*)d_induced)[q];
    else         v = *((const float4*)(emb + (size_t)tok * EDIM) + q);
    ((float4*)d_e2)[gid] = v;
}

// ---- xi GEMM v2 (unchanged): full-tile staging, 2-timestep blocking ----
__global__ void __launch_bounds__(512) xi_gemm_kernel(const float* __restrict__ W_ih,
                                                      const float* __restrict__ b_ih) {
    extern __shared__ __align__(16) float xs[];
    float* w_s = xs;                       // [128][256]
    float* e_s = xs + 128 * 256;           // [64][260]
    int t0 = blockIdx.x * 2;
    int g0 = blockIdx.y * 128;
    int tid = threadIdx.x;
    int w = tid >> 5, lane = tid & 31;

    for (int f = tid; f < 128 * 256; f += 512)
        w_s[f] = W_ih[(size_t)(g0 + (f >> 8)) * EDIM + (f & 255)];
    const float* esrc = d_e2 + (size_t)t0 * BATCH * EDIM;
    for (int f = tid; f < 64 * 256; f += 512)
        e_s[(f >> 8) * 260 + (f & 255)] = esrc[f];
    __syncthreads();

    unsigned long long a0[8], a1[8];
    #pragma unroll
    for (int g = 0; g < 8; g++) { a0[g] = 0ull; a1[g] = 0ull; }

    const float* h0 = e_s + lane * 260;
    const float* h1 = e_s + (32 + lane) * 260;
    const float* wb = w_s + (w * 8) * 256;
    #pragma unroll 8
    for (int k4 = 0; k4 < 256; k4 += 4) {
        ulonglong2 hv0 = *(const ulonglong2*)(h0 + k4);
        ulonglong2 hv1 = *(const ulonglong2*)(h1 + k4);
        #pragma unroll
        for (int g = 0; g < 8; g++) {
            ulonglong2 wv = *(const ulonglong2*)(wb + g * 256 + k4);
            fma2(a0[g], hv0.x, wv.x);
            fma2(a0[g], hv0.y, wv.y);
            fma2(a1[g], hv1.x, wv.x);
            fma2(a1[g], hv1.y, wv.y);
        }
    }
    #pragma unroll
    for (int g = 0; g < 8; g++) {
        int gg = g0 + w * 8 + g;
        float bias = b_ih[gg];
        float2 p0 = upk(a0[g]);
        float2 p1 = upk(a1[g]);
        d_xi[((size_t)t0 * G3 + gg) * BATCH + lane]       = p0.x + p0.y + bias;
        d_xi[((size_t)(t0 + 1) * G3 + gg) * BATCH + lane] = p1.x + p1.y + bias;
    }
}

// ---- GRU v9: 4 independent batch groups, 32-CTA barriers, h reuse in smem ----
// group g = bid>>5 owns batches 8g..8g+7; CTA lc = bid&31 owns dims 16lc..16lc+15
// (48 W_hh rows, 96KB stationary). Warps 0-11: dot (row = 4w+(lane>>3), b=lane&7,
// full 512-K dot, 4 rotating accs). Warps 12-15: finalize (dl=(w-12)*4+(lane>>3)).
__global__ void __launch_bounds__(GRUT, 1)
gru_kernel(const float* __restrict__ W_hh, const float* __restrict__ b_hh) {
    extern __shared__ float sm[];
    float* w_s = sm;                        // [48][516]  (99072 B)
    float* h_s = sm + 48 * 516;             // [8][516]   (16512 B)
    float* red = h_s + 8 * 516;             // [48][8]    ( 1536 B)

    const int tid  = threadIdx.x;
    const int w    = tid >> 5, lane = tid & 31;
    const int g    = blockIdx.x >> 5, lc = blockIdx.x & 31;

    // stage 48 weight rows: row r = gate*16 + dl  ->  W_hh[gate*512 + 16lc+dl]
    for (int f = tid; f < 48 * 512; f += GRUT) {
        int r = f >> 9, k = f & 511;
        w_s[r * 516 + k] = W_hh[((size_t)(r >> 4) * HDIM + lc * DPC2 + (r & 15)) * HDIM + k];
    }

    float bh0 = 0.f, bh1 = 0.f, bh2 = 0.f;
    int d = 0, bg = 0, dl = 0, bb = 0;
    if (w >= 12) {
        dl = (w - 12) * 4 + (lane >> 3);
        bb = lane & 7;
        d  = lc * DPC2 + dl;
        bg = g * BPG + bb;
        bh0 = b_hh[d]; bh1 = b_hh[HDIM + d]; bh2 = b_hh[2 * HDIM + d];
    }
    unsigned* cnt = &d_cntg[g * 32];
    unsigned* gen = &d_geng[g * 32];
    float maxacc = -INFINITY;
    float hp = 0.f;                          // own h[d][b], register-carried
    __syncthreads();

    for (int t = 0; t < SEQ; t++) {
        // 1) stage this group's h (512d x 8b = 16KB), coalesced .cg float4
        const float4* hb = (const float4*)(d_h3 + ((size_t)((t & 1) * NG + g)) * BPG * HDIM);
        {
            float4 v0 = ldcg4(hb + tid);
            float4 v1 = ldcg4(hb + tid + 512);
            int b0 = tid >> 7, k0 = tid & 127;
            *(float4*)(h_s + b0 * 516 + k0 * 4) = v0;
            int f1 = tid + 512;
            int b1 = f1 >> 7, k1 = f1 & 127;
            *(float4*)(h_s + b1 * 516 + k1 * 4) = v1;
        }
        // finalize warps: prefetch xi[t] meanwhile (independent of h)
        float xr = 0.f, xz = 0.f, xn = 0.f;
        if (w >= 12) {
            const float* xib = d_xi + (size_t)t * G3 * BATCH;
            xr = xib[(size_t)(0 * HDIM + d) * BATCH + bg];
            xz = xib[(size_t)(1 * HDIM + d) * BATCH + bg];
            xn = xib[(size_t)(2 * HDIM + d) * BATCH + bg];
        }
        __syncthreads();

        // 2) dot warps: full 512-K dot per (row, b), 4 rotating f32x2 accs
        if (w < 12) {
            int row = 4 * w + (lane >> 3);
            int b   = lane & 7;
            const float* hr = h_s + b * 516;
            const float* wr = w_s + row * 516;
            unsigned long long a0 = 0ull, a1 = 0ull, a2 = 0ull, a3 = 0ull;
            #pragma unroll 8
            for (int k = 0; k < 512; k += 8) {
                ulonglong2 hv0 = *(const ulonglong2*)(hr + k);
                ulonglong2 hv1 = *(const ulonglong2*)(hr + k + 4);
                ulonglong2 wv0 = *(const ulonglong2*)(wr + k);
                ulonglong2 wv1 = *(const ulonglong2*)(wr + k + 4);
                fma2(a0, hv0.x, wv0.x);
                fma2(a1, hv0.y, wv0.y);
                fma2(a2, hv1.x, wv1.x);
                fma2(a3, hv1.y, wv1.y);
            }
            float2 p0 = upk(a0), p1 = upk(a1), p2 = upk(a2), p3 = upk(a3);
            red[row * 8 + b] = (p0.x + p0.y) + (p1.x + p1.y)
                             + (p2.x + p2.y) + (p3.x + p3.y);
        }
        __syncthreads();

        // 3) finalize (warps 12-15): gates + h publish
        if (w >= 12) {
            float sr = red[(0 * DPC2 + dl) * 8 + bb];
            float sz = red[(1 * DPC2 + dl) * 8 + bb];
            float sn = red[(2 * DPC2 + dl) * 8 + bb];
            float rg = 0.5f * tanh_ap(0.5f * (xr + sr + bh0)) + 0.5f;
            float zg = 0.5f * tanh_ap(0.5f * (xz + sz + bh1)) + 0.5f;
            float ng = tanh_ap(xn + rg * (sn + bh2));    // torch: b_hh_n inside r*(.)
            float hnew = (1.f - zg) * ng + zg * hp;
            maxacc = fmaxf(maxacc, hnew);
            hp = hnew;
            stcg(d_h3 + ((size_t)(((t + 1) & 1) * NG + g) * BPG + bb) * HDIM + d, hnew);
            __threadfence();                 // writers only
        }
        __syncthreads();

        // 4) per-group barrier (32 CTAs; proven atomic arrival + release)
        if (t < SEQ - 1) {
            if (tid == 0) {
                unsigned step = (unsigned)(t + 1);
                unsigned target = (unsigned)CPG * step;
                unsigned a = atomicAdd(cnt, 1u) + 1u;
                if (a == target) {
                    atomicExch(gen, step);
                } else {
                    while (*((volatile unsigned*)gen) < step) { }
                }
            }
            __syncthreads();
        }
    }
    if (w >= 12) d_pooled[bg * HDIM + d] = maxacc;
}

// ---- projection: out[b][c] = pooled[b] . W_proj[c] + b_proj[c] ----
__global__ void proj_kernel(const float* __restrict__ Wp,
                            const float* __restrict__ bp,
                            float* __restrict__ out) {
    __shared__ float red[128];
    int b = blockIdx.x >> 1, c = blockIdx.x & 1;
    int tid = threadIdx.x;
    const float* pr = d_pooled + b * HDIM;
    const float* wr = Wp + c * HDIM;
    float s = 0.f;
    for (int k = tid; k < HDIM; k += 128) s += pr[k] * wr[k];
    red[tid] = s;
    __syncthreads();
    for (int off = 64; off > 0; off >>= 1) {
        if (tid < off) red[tid] += red[tid + off];
        __syncthreads();
    }
    if (tid == 0) out[b * 2 + c] = red[0] + bp[c];
}

extern "C" void kernel_launch(void* const* d_in, const int* in_sizes, int n_in,
                              void* d_out, int out_size) {
    const int*   x     = (const int*)  d_in[0];
    const float* emb   = (const float*)d_in[1];
    const float* unk   = (const float*)d_in[2];
    const float* induc = (const float*)d_in[3];
    const float* W_ih  = (const float*)d_in[4];
    const float* W_hh  = (const float*)d_in[5];
    const float* b_ih  = (const float*)d_in[6];
    const float* b_hh  = (const float*)d_in[7];
    const float* W_pr  = (const float*)d_in[8];
    const float* b_pr  = (const float*)d_in[9];
    float* out = (float*)d_out;

    size_t xi_smem  = (128 * 256 + 64 * 260) * sizeof(float);         // 197632 B
    size_t gru_smem = (48 * 516 + 8 * 516 + 48 * 8) * sizeof(float);  // 117120 B
    cudaFuncSetAttribute(xi_gemm_kernel, cudaFuncAttributeMaxDynamicSharedMemorySize,
                         (int)xi_smem);
    cudaFuncSetAttribute(gru_kernel, cudaFuncAttributeMaxDynamicSharedMemorySize,
                         (int)gru_smem);

    init_kernel<<<1, 256>>>(induc, unk);
    gather_kernel<<<(SEQ * BATCH * 64) / 256, 256>>>(x, emb);
    dim3 gg(SEQ / 2, G3 / 128);
    xi_gemm_kernel<<<gg, 512, xi_smem>>>(W_ih, b_ih);
    gru_kernel<<<NCTA, GRUT, gru_smem>>>(W_hh, b_hh);
    proj_kernel<<<BATCH * 2, 128>>>(W_pr, b_pr, out);
}